// round 3
// baseline (speedup 1.0000x reference)
#include <cuda_runtime.h>
#include <cuda_bf16.h>

// y[b][t][c] = d[c]*y[b][t-1][c] + x[b][t][c],  y[b][0][c] = x[b][0][c]
// x: [8, 4096, 1024] fp32, d: [1024] fp32.
//
// Single-pass chained-lookback scan:
//   grid = (256 chains = batch*channel_tile, 16 time-chunks)
//   block = 32 lanes (channels) x 8 warps (time), chunk = 256 timesteps,
//   32 steps per thread held in registers.
// Per block: load -> local chunk scan (registers) -> 8-way smem fold ->
//   consume predecessor chunk carry (32 floats via L2, spin on flag) ->
//   publish own inclusive carry -> apply prefix in register pass-2 -> store.
// x read once, y written once: 256 MiB total HBM traffic.
// Flags are reset by their unique consumer => safe across graph replays.

#define BB     8
#define TT     4096
#define CC     1024
#define CT     32              // channels per block
#define NW     8               // time-warps per block
#define STEPS  32              // timesteps per thread
#define SEG    (NW * STEPS)    // 256 timesteps per chunk
#define NTC    (TT / SEG)      // 16 time-chunks
#define CHAINS (BB * (CC / CT))// 256 chains

__device__ float        g_carry[NTC - 1][CHAINS][CT];
__device__ unsigned int g_flag[NTC - 1][CHAINS];

__global__ void __launch_bounds__(CT * NW, 2)
cummulsum_lookback_kernel(const float* __restrict__ x,
                          const float* __restrict__ d,
                          float* __restrict__ y)
{
    __shared__ float scarry[NW][CT];
    __shared__ float sinc[CT];

    const int lane  = threadIdx.x;          // channel lane 0..31
    const int ty    = threadIdx.y;          // time-warp 0..7
    const int chain = blockIdx.x;           // 0..255  (b*32 + cb)
    const int tc    = blockIdx.y;           // 0..15   (slowest-varying)
    const int b     = chain >> 5;
    const int cb    = chain & 31;
    const int c     = cb * CT + lane;

    const float dd = d[c];
    float dS = dd;                          // d^32 via 5 squarings
    #pragma unroll
    for (int i = 0; i < 5; i++) dS = dS * dS;

    const size_t t0 = (size_t)tc * SEG + (size_t)ty * STEPS;
    const float* xp = x + ((size_t)b * TT + t0) * CC + c;
    float*       yp = y + ((size_t)b * TT + t0) * CC + c;

    // Load 32 timesteps into registers (coalesced 128B per warp per step)
    float xa[STEPS];
    #pragma unroll
    for (int i = 0; i < STEPS; i++) xa[i] = xp[(size_t)i * CC];

    // Pass 1: warp-chunk carry with zero initial state
    float cr = xa[0];
    #pragma unroll
    for (int i = 1; i < STEPS; i++) cr = fmaf(dd, cr, xa[i]);
    scarry[ty][lane] = cr;

    // Warp 0 performs the lookback while results settle
    if (ty == 0) {
        if (tc > 0) {
            if (lane == 0) {
                volatile unsigned int* f = &g_flag[tc - 1][chain];
                while (*f == 0u) { }
            }
            __syncwarp();
            __threadfence();
            sinc[lane] = g_carry[tc - 1][chain][lane];
            __syncwarp();
            if (lane == 0) g_flag[tc - 1][chain] = 0u;  // reset for next launch
        } else {
            sinc[lane] = 0.0f;
        }
    }
    __syncthreads();

    // Fold: every thread walks the 8 warp carries with ratio d^32,
    // starting from the incoming chain prefix.
    float p   = sinc[lane];
    float myp = p;                 // prefix for ty==0
    #pragma unroll
    for (int w = 0; w < NW; w++) {
        const float cw = scarry[w][lane];
        p = fmaf(dS, p, cw);
        if (w == ty - 1) myp = p;
    }

    // Publish inclusive chunk carry for the successor chunk
    if (tc < NTC - 1 && ty == 0) {
        g_carry[tc][chain][lane] = p;
        __threadfence();
        if (lane == 0) atomicExch(&g_flag[tc][chain], 1u);
    }

    // Pass 2: re-scan from the prefix using register-resident x, store y
    float yv = myp;
    #pragma unroll
    for (int i = 0; i < STEPS; i++) {
        yv = fmaf(dd, yv, xa[i]);
        yp[(size_t)i * CC] = yv;
    }
}

extern "C" void kernel_launch(void* const* d_in, const int* in_sizes, int n_in,
                              void* d_out, int out_size)
{
    const float* x = (const float*)d_in[0];
    const float* d = (const float*)d_in[1];
    if (n_in >= 2 && in_sizes[0] < in_sizes[1]) {   // identify by size
        x = (const float*)d_in[1];
        d = (const float*)d_in[0];
    }
    float* y = (float*)d_out;

    dim3 grid(CHAINS, NTC);   // (256, 16) = 4096 blocks; tc slowest-varying
    dim3 block(CT, NW);       // (32, 8) = 256 threads
    cummulsum_lookback_kernel<<<grid, block>>>(x, d, y);
}

// round 4
// speedup vs baseline: 1.4982x; 1.4982x over previous
#include <cuda_runtime.h>
#include <cuda_bf16.h>

// y[b][t][c] = d[c]*y[b][t-1][c] + x[b][t][c],  y[b][0][c] = x[b][0][c]
// x: [8, 4096, 1024] fp32, d: [1024] fp32.
//
// One persistent block per (batch, 32-channel tile) chain — 256 blocks,
// 512 threads each (32 channel lanes x 16 time-warps). Block walks time in
// 16 segments of 256 steps; each thread scans 16 steps in registers
// (double-buffered prefetch one segment ahead), a 16-way smem fold with
// ratio d^16 propagates the per-channel carry, then a register-resident
// second pass applies the prefix and stores y.
// x read from HBM exactly once, y written once: 256 MiB total traffic.

#define BB    8
#define TT    4096
#define CC    1024
#define CT    32                 // channels per block (= warp lanes)
#define NW    16                 // time-warps per block
#define STEPS 16                 // timesteps per thread per segment
#define SEG   (NW * STEPS)       // 256 timesteps per segment
#define NSEG  (TT / SEG)         // 16 segments

__device__ __forceinline__ void segment_body(
    int s, bool prefetch,
    float (&cur)[STEPS], float (&nxt)[STEPS],
    const float* __restrict__ xbase, float* __restrict__ ybase,
    float dd, float dS, float& bc,
    float (*scarry)[NW][CT], int lane, int ty)
{
    // Prefetch next segment (independent of the carry chain)
    if (prefetch) {
        const float* p1 = xbase + (size_t)((s + 1) * SEG + ty * STEPS) * CC;
        #pragma unroll
        for (int i = 0; i < STEPS; i++) nxt[i] = p1[(size_t)i * CC];
    }

    // Pass 1: warp-chunk carry (scan of 16 steps with y_in = 0)
    float cr = cur[0];
    #pragma unroll
    for (int i = 1; i < STEPS; i++) cr = fmaf(dd, cr, cur[i]);

    const int par = s & 1;
    scarry[par][ty][lane] = cr;
    __syncthreads();

    // Fold: every thread walks the 16 chunk carries with ratio d^16.
    //   p after folding chunks 0..w == prefix for time-warp w+1
    //   p after folding all 16     == next block carry (stays in a register)
    float p   = bc;
    float myp = bc;   // prefix for ty==0
    #pragma unroll
    for (int w = 0; w < NW; w++) {
        const float cw = scarry[par][w][lane];
        p = fmaf(dS, p, cw);
        if (w == ty - 1) myp = p;
    }
    bc = p;

    // Pass 2: re-scan from prefix using register-resident x, store y
    float yv = myp;
    float* po = ybase + (size_t)(s * SEG + ty * STEPS) * CC;
    #pragma unroll
    for (int i = 0; i < STEPS; i++) {
        yv = fmaf(dd, yv, cur[i]);
        po[(size_t)i * CC] = yv;
    }
}

__global__ void __launch_bounds__(CT * NW, 2)
cummulsum_kernel(const float* __restrict__ x,
                 const float* __restrict__ d,
                 float* __restrict__ y)
{
    __shared__ float scarry[2][NW][CT];

    const int lane = threadIdx.x;            // channel lane 0..31
    const int ty   = threadIdx.y;            // time-warp 0..15
    const int c    = blockIdx.x * CT + lane; // channel
    const int b    = blockIdx.y;             // batch

    const float dd = d[c];
    // dS = d^STEPS = d^16 via 4 squarings
    float dS = dd;
    #pragma unroll
    for (int i = 0; i < 4; i++) dS = dS * dS;

    const float* xbase = x + ((size_t)b * TT) * CC + c;
    float*       ybase = y + ((size_t)b * TT) * CC + c;

    float xa[STEPS], xn[STEPS];

    // Load segment 0
    {
        const float* p0 = xbase + (size_t)(ty * STEPS) * CC;
        #pragma unroll
        for (int i = 0; i < STEPS; i++) xa[i] = p0[(size_t)i * CC];
    }

    float bc = 0.0f;   // block carry: y value just before current segment

    // Unrolled by 2 to ping-pong register buffers without copies
    for (int s = 0; s < NSEG; s += 2) {
        segment_body(s,     true,            xa, xn, xbase, ybase,
                     dd, dS, bc, scarry, lane, ty);
        segment_body(s + 1, (s + 2) < NSEG,  xn, xa, xbase, ybase,
                     dd, dS, bc, scarry, lane, ty);
    }
}

extern "C" void kernel_launch(void* const* d_in, const int* in_sizes, int n_in,
                              void* d_out, int out_size)
{
    const float* x = (const float*)d_in[0];
    const float* d = (const float*)d_in[1];
    if (n_in >= 2 && in_sizes[0] < in_sizes[1]) {   // identify by size
        x = (const float*)d_in[1];
        d = (const float*)d_in[0];
    }
    float* y = (float*)d_out;

    dim3 grid(CC / CT, BB);   // (32, 8) = 256 blocks, single wave
    dim3 block(CT, NW);       // (32, 16) = 512 threads
    cummulsum_kernel<<<grid, block>>>(x, d, y);
}